// round 8
// baseline (speedup 1.0000x reference)
#include <cuda_runtime.h>
#include <cuda_fp16.h>

#define BB 32
#define NN 1024
#define GG 8
#define HH 128

// ---- prepped fp16 weight images, ldmatrix-swizzled k64 chunks ----
// chunk: 64 k-rows x 128 n-cols fp16, 256B rows; 16B col-chunk XOR-swizzled by (k&7).
__device__ __align__(16) unsigned char gBd[16 * 16384];   // W0 rows 9..1032 (dots)
__device__ __align__(16) unsigned char gW1[2 * 16384];
__device__ __align__(16) unsigned char gW2[2 * 16384];

// ---- smem map (bytes) ----
#define OFF_A0   0        // layer0 A buf0 (128x64 fp16, 128B rows)  | H plane low half
#define OFF_A1   16384    // layer0 A buf1                           | H plane high half
#define OFF_B0   32768    // layer0 B buf0 / W chunk0
#define OFF_B1   49152    // layer0 B buf1 / W chunk1
#define OFF_XALL 65536    // x[b] fp32 [1024][3] = 12288 B
#define OFF_NRM  77824
#define OFF_CU   78336
#define OFF_W0N  78848
#define OFF_B1S  79360
#define OFF_B2S  79872
#define OFF_OACC 80384    // fp32 [128][3]
#define SMEM_BYTES 81920

// ---------------- helpers ----------------
__device__ __forceinline__ unsigned smem_u32(const void* p) {
    unsigned a;
    asm("{ .reg .u64 t; cvta.to.shared.u64 t, %1; cvt.u32.u64 %0, t; }" : "=r"(a) : "l"(p));
    return a;
}
__device__ __forceinline__ void ldsm_x4(unsigned* r, unsigned a) {
    asm volatile("ldmatrix.sync.aligned.m8n8.x4.shared.b16 {%0,%1,%2,%3}, [%4];"
                 : "=r"(r[0]), "=r"(r[1]), "=r"(r[2]), "=r"(r[3]) : "r"(a));
}
__device__ __forceinline__ void ldsm_x4t(unsigned* r, unsigned a) {
    asm volatile("ldmatrix.sync.aligned.m8n8.x4.trans.shared.b16 {%0,%1,%2,%3}, [%4];"
                 : "=r"(r[0]), "=r"(r[1]), "=r"(r[2]), "=r"(r[3]) : "r"(a));
}
__device__ __forceinline__ void mma16816(float* d, const unsigned* a, unsigned b0, unsigned b1) {
    asm volatile(
        "mma.sync.aligned.m16n8k16.row.col.f32.f16.f16.f32 "
        "{%0,%1,%2,%3}, {%4,%5,%6,%7}, {%8,%9}, {%0,%1,%2,%3};"
        : "+f"(d[0]), "+f"(d[1]), "+f"(d[2]), "+f"(d[3])
        : "r"(a[0]), "r"(a[1]), "r"(a[2]), "r"(a[3]), "r"(b0), "r"(b1));
}
__device__ __forceinline__ void cpa16(unsigned dst, const void* src) {
    asm volatile("cp.async.cg.shared.global [%0], [%1], 16;" :: "r"(dst), "l"(src));
}
__device__ __forceinline__ void cpa_wait_all() {
    asm volatile("cp.async.wait_all;" ::: "memory");
}
__device__ __forceinline__ float asqrt(float v) {   // MUFU.SQRT
    float r;
    asm("sqrt.approx.f32 %0, %1;" : "=f"(r) : "f"(v));
    return r;
}
__device__ __forceinline__ float leaky(float v) { return v > 0.0f ? v : 0.01f * v; }
__device__ __forceinline__ unsigned short h16(float v) {
    __half h = __float2half_rn(v);
    return *(unsigned short*)&h;
}

// k64 MMA sweep (1-term): acc[m*8+nfl] += A x B.
// Warp = (rg, cg): rows rg*32 + m*16, cols cg*64 + nfl*8.
template<int RSTRIDE>
__device__ __forceinline__ void mma_k64(float (&acc)[16][4], unsigned aBase, unsigned bBase,
                                        int kOff, int rg, int cg, int lane) {
    const int il  = lane & 15;
    const int kq  = lane >> 4;
    const int kkl = lane & 15;
    const int kx  = lane & 7;
    const int nfs = lane >> 4;
    #pragma unroll
    for (int ks = 0; ks < 64; ks += 16) {
        const int kc = ((kOff + ks) >> 3) + kq;
        unsigned a[2][4];
        #pragma unroll
        for (int m = 0; m < 2; m++) {
            const int i = rg * 32 + m * 16 + il;
            ldsm_x4(a[m], aBase + i * RSTRIDE + ((unsigned)(kc ^ (i & 7)) << 4));
        }
        const unsigned bbase = (unsigned)(ks + kkl) * 256;
        unsigned bb[16];
        #pragma unroll
        for (int p = 0; p < 4; p++) {
            const int nf = cg * 8 + p * 2 + nfs;
            ldsm_x4t(bb + p * 4, bBase + bbase + ((unsigned)(nf ^ kx) << 4));
        }
        #pragma unroll
        for (int p = 0; p < 4; p++) {
            #pragma unroll
            for (int m = 0; m < 2; m++) {
                mma16816(acc[m * 8 + p * 2 + 0], a[m], bb[p * 4 + 0], bb[p * 4 + 1]);
                mma16816(acc[m * 8 + p * 2 + 1], a[m], bb[p * 4 + 2], bb[p * 4 + 3]);
            }
        }
    }
}

// Epilogue: leaky + fp16 into h plane (256B rows), re-init acc with bias.
__device__ __forceinline__ void epi_split(float (&acc)[16][4], unsigned char* dH,
                                          const float* nb, int rg, int cg, int lane) {
    const int cp = lane & 3, r8 = lane >> 2;
    #pragma unroll
    for (int m = 0; m < 2; m++) {
        const int r1 = rg * 32 + m * 16 + r8, r2 = r1 + 8;
        #pragma unroll
        for (int nfl = 0; nfl < 8; nfl++) {
            float* A = acc[m * 8 + nfl];
            const int c = cg * 64 + nfl * 8 + cp * 2;
            unsigned short a0 = h16(leaky(A[0])), a1 = h16(leaky(A[1]));
            unsigned short a2 = h16(leaky(A[2])), a3 = h16(leaky(A[3]));
            const unsigned o1 = r1 * 256 + ((unsigned)(((c >> 3) ^ (r1 & 7))) << 4) + (c & 7) * 2;
            const unsigned o2 = r2 * 256 + ((unsigned)(((c >> 3) ^ (r2 & 7))) << 4) + (c & 7) * 2;
            *(unsigned*)(dH + o1) = (unsigned)a0 | ((unsigned)a1 << 16);
            *(unsigned*)(dH + o2) = (unsigned)a2 | ((unsigned)a3 << 16);
            A[0] = nb[c]; A[1] = nb[c + 1]; A[2] = nb[c]; A[3] = nb[c + 1];
        }
    }
}

// ---------------------------------------------------------------------------
// Prep (+ output zero): round weights to fp16 into swizzled chunk images.
__global__ void k_prep(const float* __restrict__ W0, const float* __restrict__ W1,
                       const float* __restrict__ W2, float* __restrict__ out) {
    int idx = blockIdx.x * 256 + threadIdx.x;
    float v; unsigned char* dp;
    int k, n;
    if (idx < 131072) {                   // dots rows of W0
        k = idx >> 7; n = idx & 127;
        v = W0[(9 + k) * HH + n];
        dp = gBd;
    } else if (idx < 147456) {            // W1
        int t = idx - 131072;
        k = t >> 7; n = t & 127;
        v = W1[k * HH + n];
        dp = gW1;
    } else if (idx < 163840) {            // W2
        int t = idx - 147456;
        k = t >> 7; n = t & 127;
        v = W2[k * HH + n];
        dp = gW2;
    } else {
        int t = idx - 163840;
        if (t < BB * HH * 3) out[t] = 0.0f;
        return;
    }
    const int cb = k >> 6, kl = k & 63;
    const unsigned off = cb * 16384 + kl * 256 + ((((n >> 3) ^ (kl & 7))) << 4) + (n & 7) * 2;
    *(unsigned short*)(dp + off) = h16(v);
}

// ---------------------------------------------------------------------------
__global__ void __launch_bounds__(256, 2)
k_main(const float* __restrict__ x, const float* __restrict__ u,
       const float* __restrict__ W0, const float* __restrict__ b0,
       const float* __restrict__ b1, const float* __restrict__ b2,
       float* __restrict__ out)
{
    extern __shared__ __align__(1024) unsigned char smem[];
    const unsigned sb = smem_u32(smem);
    const int tid = threadIdx.x, w = tid >> 5, lane = tid & 31;
    const int rg = w & 3, cg = w >> 2;
    const int b = blockIdx.x >> 3, i0 = (blockIdx.x & 7) * 128;

    float* xall = (float*)(smem + OFF_XALL);
    float* nrm  = (float*)(smem + OFF_NRM);
    float* cu   = (float*)(smem + OFF_CU);
    float* w0n  = (float*)(smem + OFF_W0N);
    float* b1s  = (float*)(smem + OFF_B1S);
    float* b2s  = (float*)(smem + OFF_B2S);
    float* oacc = (float*)(smem + OFF_OACC);

    // prologue: whole-batch x into smem (12 KB), biases, cu
    {
        const float4* src = (const float4*)(x + (size_t)b * NN * 3);
        float4* dst = (float4*)xall;
        #pragma unroll
        for (int m = 0; m < 3; m++) dst[tid + m * 256] = src[tid + m * 256];
    }
    if (tid < 128) {
        float s = b0[tid];
        #pragma unroll
        for (int g = 0; g < GG; g++) s += u[b * GG + g] * W0[g * HH + tid];
        cu[tid]  = s;
        w0n[tid] = W0[8 * HH + tid];
        b1s[tid] = b1[tid];
        b2s[tid] = b2[tid];
    }
    for (int t = tid; t < 384; t += 256) oacc[t] = 0.0f;
    __syncthreads();
    if (tid < 128) {
        const float* y = xall + (size_t)(i0 + tid) * 3;
        nrm[tid] = asqrt(y[0] * y[0] + y[1] * y[1] + y[2] * y[2]);
    }
    __syncthreads();

    // acc[m*8+nfl][4]: rows rg*32 + m*16 (+r8/+8), cols cg*64 + nfl*8 (+cp*2)
    float acc[16][4];
    {
        const int cp = lane & 3, r8 = lane >> 2;
        #pragma unroll
        for (int m = 0; m < 2; m++) {
            const int r1 = rg * 32 + m * 16 + r8, r2 = r1 + 8;
            const float n1 = nrm[r1], n2 = nrm[r2];
            #pragma unroll
            for (int nfl = 0; nfl < 8; nfl++) {
                const int c = cg * 64 + nfl * 8 + cp * 2;
                float* A = acc[m * 8 + nfl];
                A[0] = cu[c]     + n1 * w0n[c];
                A[1] = cu[c + 1] + n1 * w0n[c + 1];
                A[2] = cu[c]     + n2 * w0n[c];
                A[3] = cu[c + 1] + n2 * w0n[c + 1];
            }
        }
    }

    const int jj2 = (tid & 31) * 2;   // j pair base 0..62
    const int ig  = tid >> 5;         // row group 0..7 (16 rows each)
    const unsigned csw = (unsigned)(jj2 >> 3) << 4;
    const unsigned cby = (unsigned)(jj2 & 7) * 2;

    // gen sqrt-gram A tile for chunk cb into aT (xj read from smem)
    auto gen = [&](int cb, unsigned char* aT) {
        const float* xj = xall + (size_t)(cb * 64 + jj2) * 3;
        const float xa0 = xj[0], xa1 = xj[1], xa2 = xj[2];
        const float xb0 = xj[3], xb1 = xj[4], xb2 = xj[5];
        #pragma unroll 4
        for (int it = 0; it < 16; it++) {
            const int i = ig * 16 + it;
            const float* y = xall + (size_t)(i0 + i) * 3;
            const float y0 = y[0], y1 = y[1], y2 = y[2];
            float s0 = asqrt(y0 * xa0 + y1 * xa1 + y2 * xa2);
            float s1 = asqrt(y0 * xb0 + y1 * xb1 + y2 * xb2);
            __half2 hv = __floats2half2_rn(s0, s1);
            const unsigned off = i * 128 + (csw ^ ((unsigned)(i & 7) << 4)) + cby;
            *(unsigned*)(aT + off) = *(unsigned*)&hv;
        }
    };
    auto copy16k = [&](const unsigned char* src, unsigned dst) {
        src += tid * 16; dst += tid * 16;
        #pragma unroll
        for (int m = 0; m < 4; m++) cpa16(dst + m * 4096, src + m * 4096);
    };

    const unsigned bufA[2] = { sb + OFF_A0, sb + OFF_A1 };
    const unsigned bufB[2] = { sb + OFF_B0, sb + OFF_B1 };

    // pipeline prologue: chunk 0
    copy16k(gBd, bufB[0]);
    gen(0, smem + OFF_A0);
    cpa_wait_all();
    __syncthreads();

    // ---------------- layer 0 pipelined mainloop ----------------
    for (int cb = 0; cb < 16; cb++) {
        const int cur = cb & 1, nxt = cur ^ 1;
        if (cb < 15) {
            copy16k(gBd + (cb + 1) * 16384, bufB[nxt]);
            gen(cb + 1, smem + (nxt ? OFF_A1 : OFF_A0));
        } else {
            copy16k(gW1, bufB[0]);     // prefetch W1 chunk0 (B0 free: last read at cb=14)
        }
        mma_k64<128>(acc, bufA[cur], bufB[cur], 0, rg, cg, lane);
        cpa_wait_all();
        __syncthreads();
    }

    // ---------------- layer 0 epilogue -> H (A region); layer 1 ----------------
    epi_split(acc, smem + OFF_A0, b1s, rg, cg, lane);
    copy16k(gW1 + 16384, bufB[1]);     // W1 chunk1 (B1 free after loop-end sync)
    cpa_wait_all();
    __syncthreads();

    mma_k64<256>(acc, bufA[0], bufB[0], 0, rg, cg, lane);
    mma_k64<256>(acc, bufA[0], bufB[1], 64, rg, cg, lane);
    __syncthreads();                   // all H/B reads done

    // ---------------- layer 1 epilogue -> H; layer 2 ----------------
    epi_split(acc, smem + OFF_A0, b2s, rg, cg, lane);
    copy16k(gW2, bufB[0]);
    copy16k(gW2 + 16384, bufB[1]);
    cpa_wait_all();
    __syncthreads();

    mma_k64<256>(acc, bufA[0], bufB[0], 0, rg, cg, lane);
    mma_k64<256>(acc, bufA[0], bufB[1], 64, rg, cg, lane);

    // ---------------- final contraction: out[b,c,d] += sum_i fk[i,c] * x[i,d] / N ------
    {
        const int r8 = lane >> 2;
        #pragma unroll
        for (int m = 0; m < 2; m++) {
            const int r1 = rg * 32 + m * 16 + r8, r2 = r1 + 8;
            const float* ya = xall + (size_t)(i0 + r1) * 3;
            const float* yb = xall + (size_t)(i0 + r2) * 3;
            const float x10 = ya[0], x11 = ya[1], x12 = ya[2];
            const float x20 = yb[0], x21 = yb[1], x22 = yb[2];
            #pragma unroll
            for (int nfl = 0; nfl < 8; nfl++) {
                float* A = acc[m * 8 + nfl];
                float s[6];
                s[0] = A[0] * x10 + A[2] * x20;
                s[1] = A[0] * x11 + A[2] * x21;
                s[2] = A[0] * x12 + A[2] * x22;
                s[3] = A[1] * x10 + A[3] * x20;
                s[4] = A[1] * x11 + A[3] * x21;
                s[5] = A[1] * x12 + A[3] * x22;
                #pragma unroll
                for (int q = 0; q < 6; q++) {
                    s[q] += __shfl_xor_sync(0xffffffffu, s[q], 4);
                    s[q] += __shfl_xor_sync(0xffffffffu, s[q], 8);
                    s[q] += __shfl_xor_sync(0xffffffffu, s[q], 16);
                }
                if (lane < 4) {
                    const int c = cg * 64 + nfl * 8 + lane * 2;
                    atomicAdd(&oacc[c * 3 + 0], s[0]);
                    atomicAdd(&oacc[c * 3 + 1], s[1]);
                    atomicAdd(&oacc[c * 3 + 2], s[2]);
                    atomicAdd(&oacc[(c + 1) * 3 + 0], s[3]);
                    atomicAdd(&oacc[(c + 1) * 3 + 1], s[4]);
                    atomicAdd(&oacc[(c + 1) * 3 + 2], s[5]);
                }
            }
        }
    }
    __syncthreads();
    const float inv = 1.0f / (float)NN;
    for (int t = tid; t < 384; t += 256)
        atomicAdd(out + (size_t)b * 384 + t, oacc[t] * inv);
}

// ---------------------------------------------------------------------------
extern "C" void kernel_launch(void* const* d_in, const int* in_sizes, int n_in,
                              void* d_out, int out_size) {
    const float* x  = (const float*)d_in[0];
    const float* u  = (const float*)d_in[1];
    const float* W0 = (const float*)d_in[2];
    const float* b0 = (const float*)d_in[3];
    const float* W1 = (const float*)d_in[4];
    const float* b1 = (const float*)d_in[5];
    const float* W2 = (const float*)d_in[6];
    const float* b2 = (const float*)d_in[7];
    float* out = (float*)d_out;

    cudaFuncSetAttribute(k_main, cudaFuncAttributeMaxDynamicSharedMemorySize, SMEM_BYTES);

    k_prep<<<688, 256>>>(W0, W1, W2, out);
    k_main<<<BB * (NN / 128), 256, SMEM_BYTES>>>(x, u, W0, b0, b1, b2, out);
}

// round 9
// speedup vs baseline: 1.0810x; 1.0810x over previous
#include <cuda_runtime.h>
#include <cuda_fp16.h>

#define BB 32
#define NN 1024
#define GG 8
#define HH 128

// ---- prepped fp16 weight images, ldmatrix-swizzled k64 chunks ----
__device__ __align__(16) unsigned char gBd[16 * 16384];   // W0 rows 9..1032 (dots)
__device__ __align__(16) unsigned char gW1[2 * 16384];
__device__ __align__(16) unsigned char gW2[2 * 16384];

// ---- smem map (bytes) ----
#define OFF_BJ   0        // dot B-frag image: 128 jblocks x 128B = 16KB   [layer0]
#define OFF_H    0        // h plane (128x128 fp16, 256B rows) 32KB        [layer phase]
#define OFF_B0   32768    // W0 chunk buf0 / W chunk0
#define OFF_B1   49152    // W0 chunk buf1 / W chunk1
#define OFF_XALL 65536    // x[b] fp32 [1024][3] = 12288 B
#define OFF_NRM  77824
#define OFF_CU   78336
#define OFF_W0N  78848
#define OFF_B1S  79360
#define OFF_B2S  79872
#define OFF_OACC 80384    // fp32 [128][3]
#define SMEM_BYTES 81920

// ---------------- helpers ----------------
__device__ __forceinline__ unsigned smem_u32(const void* p) {
    unsigned a;
    asm("{ .reg .u64 t; cvta.to.shared.u64 t, %1; cvt.u32.u64 %0, t; }" : "=r"(a) : "l"(p));
    return a;
}
__device__ __forceinline__ void ldsm_x4(unsigned* r, unsigned a) {
    asm volatile("ldmatrix.sync.aligned.m8n8.x4.shared.b16 {%0,%1,%2,%3}, [%4];"
                 : "=r"(r[0]), "=r"(r[1]), "=r"(r[2]), "=r"(r[3]) : "r"(a));
}
__device__ __forceinline__ void ldsm_x4t(unsigned* r, unsigned a) {
    asm volatile("ldmatrix.sync.aligned.m8n8.x4.trans.shared.b16 {%0,%1,%2,%3}, [%4];"
                 : "=r"(r[0]), "=r"(r[1]), "=r"(r[2]), "=r"(r[3]) : "r"(a));
}
__device__ __forceinline__ void mma16816(float* d, const unsigned* a, unsigned b0, unsigned b1) {
    asm volatile(
        "mma.sync.aligned.m16n8k16.row.col.f32.f16.f16.f32 "
        "{%0,%1,%2,%3}, {%4,%5,%6,%7}, {%8,%9}, {%0,%1,%2,%3};"
        : "+f"(d[0]), "+f"(d[1]), "+f"(d[2]), "+f"(d[3])
        : "r"(a[0]), "r"(a[1]), "r"(a[2]), "r"(a[3]), "r"(b0), "r"(b1));
}
__device__ __forceinline__ void mma16808(float* d, unsigned a0, unsigned a1, unsigned b0) {
    asm volatile(
        "mma.sync.aligned.m16n8k8.row.col.f32.f16.f16.f32 "
        "{%0,%1,%2,%3}, {%4,%5}, {%6}, {%0,%1,%2,%3};"
        : "+f"(d[0]), "+f"(d[1]), "+f"(d[2]), "+f"(d[3])
        : "r"(a0), "r"(a1), "r"(b0));
}
__device__ __forceinline__ void cpa16(unsigned dst, const void* src) {
    asm volatile("cp.async.cg.shared.global [%0], [%1], 16;" :: "r"(dst), "l"(src));
}
__device__ __forceinline__ void cpa_wait_all() {
    asm volatile("cp.async.wait_all;" ::: "memory");
}
__device__ __forceinline__ float asqrt(float v) {   // MUFU.SQRT
    float r;
    asm("sqrt.approx.f32 %0, %1;" : "=f"(r) : "f"(v));
    return r;
}
__device__ __forceinline__ float leaky(float v) { return v > 0.0f ? v : 0.01f * v; }
__device__ __forceinline__ unsigned short h16(float v) {
    __half h = __float2half_rn(v);
    return *(unsigned short*)&h;
}
__device__ __forceinline__ unsigned pack2(float a, float b) {
    __half2 h = __floats2half2_rn(a, b);
    return *(unsigned*)&h;
}

// k64 MMA sweep for layers 1/2 (A from smem H plane).
__device__ __forceinline__ void mma_k64(float (&acc)[16][4], unsigned aBase, unsigned bBase,
                                        int kOff, int rg, int cg, int lane) {
    const int il  = lane & 15;
    const int kq  = lane >> 4;
    const int kkl = lane & 15;
    const int kx  = lane & 7;
    const int nfs = lane >> 4;
    #pragma unroll
    for (int ks = 0; ks < 64; ks += 16) {
        const int kc = ((kOff + ks) >> 3) + kq;
        unsigned a[2][4];
        #pragma unroll
        for (int m = 0; m < 2; m++) {
            const int i = rg * 32 + m * 16 + il;
            ldsm_x4(a[m], aBase + i * 256 + ((unsigned)(kc ^ (i & 7)) << 4));
        }
        const unsigned bbase = (unsigned)(ks + kkl) * 256;
        unsigned bb[16];
        #pragma unroll
        for (int p = 0; p < 4; p++) {
            const int nf = cg * 8 + p * 2 + nfs;
            ldsm_x4t(bb + p * 4, bBase + bbase + ((unsigned)(nf ^ kx) << 4));
        }
        #pragma unroll
        for (int p = 0; p < 4; p++) {
            #pragma unroll
            for (int m = 0; m < 2; m++) {
                mma16816(acc[m * 8 + p * 2 + 0], a[m], bb[p * 4 + 0], bb[p * 4 + 1]);
                mma16816(acc[m * 8 + p * 2 + 1], a[m], bb[p * 4 + 2], bb[p * 4 + 3]);
            }
        }
    }
}

// Epilogue: leaky + fp16 into h plane (256B rows), re-init acc with bias.
__device__ __forceinline__ void epi_split(float (&acc)[16][4], unsigned char* dH,
                                          const float* nb, int rg, int cg, int lane) {
    const int cp = lane & 3, r8 = lane >> 2;
    #pragma unroll
    for (int m = 0; m < 2; m++) {
        const int r1 = rg * 32 + m * 16 + r8, r2 = r1 + 8;
        #pragma unroll
        for (int nfl = 0; nfl < 8; nfl++) {
            float* A = acc[m * 8 + nfl];
            const int c = cg * 64 + nfl * 8 + cp * 2;
            unsigned short a0 = h16(leaky(A[0])), a1 = h16(leaky(A[1]));
            unsigned short a2 = h16(leaky(A[2])), a3 = h16(leaky(A[3]));
            const unsigned o1 = r1 * 256 + ((unsigned)(((c >> 3) ^ (r1 & 7))) << 4) + (c & 7) * 2;
            const unsigned o2 = r2 * 256 + ((unsigned)(((c >> 3) ^ (r2 & 7))) << 4) + (c & 7) * 2;
            *(unsigned*)(dH + o1) = (unsigned)a0 | ((unsigned)a1 << 16);
            *(unsigned*)(dH + o2) = (unsigned)a2 | ((unsigned)a3 << 16);
            A[0] = nb[c]; A[1] = nb[c + 1]; A[2] = nb[c]; A[3] = nb[c + 1];
        }
    }
}

// ---------------------------------------------------------------------------
// Prep (+ output zero): round weights to fp16 into swizzled chunk images.
__global__ void k_prep(const float* __restrict__ W0, const float* __restrict__ W1,
                       const float* __restrict__ W2, float* __restrict__ out) {
    int idx = blockIdx.x * 256 + threadIdx.x;
    float v; unsigned char* dp;
    int k, n;
    if (idx < 131072) {
        k = idx >> 7; n = idx & 127;
        v = W0[(9 + k) * HH + n];
        dp = gBd;
    } else if (idx < 147456) {
        int t = idx - 131072;
        k = t >> 7; n = t & 127;
        v = W1[k * HH + n];
        dp = gW1;
    } else if (idx < 163840) {
        int t = idx - 147456;
        k = t >> 7; n = t & 127;
        v = W2[k * HH + n];
        dp = gW2;
    } else {
        int t = idx - 163840;
        if (t < BB * HH * 3) out[t] = 0.0f;
        return;
    }
    const int cb = k >> 6, kl = k & 63;
    const unsigned off = cb * 16384 + kl * 256 + ((((n >> 3) ^ (kl & 7))) << 4) + (n & 7) * 2;
    *(unsigned short*)(dp + off) = h16(v);
}

// ---------------------------------------------------------------------------
__global__ void __launch_bounds__(256, 2)
k_main(const float* __restrict__ x, const float* __restrict__ u,
       const float* __restrict__ W0, const float* __restrict__ b0,
       const float* __restrict__ b1, const float* __restrict__ b2,
       float* __restrict__ out)
{
    extern __shared__ __align__(1024) unsigned char smem[];
    const unsigned sb = smem_u32(smem);
    const int tid = threadIdx.x, w = tid >> 5, lane = tid & 31;
    const int rg = w & 3, cg = w >> 2;
    const int b = blockIdx.x >> 3, i0 = (blockIdx.x & 7) * 128;

    float* xall = (float*)(smem + OFF_XALL);
    float* nrm  = (float*)(smem + OFF_NRM);
    float* cu   = (float*)(smem + OFF_CU);
    float* w0n  = (float*)(smem + OFF_W0N);
    float* b1s  = (float*)(smem + OFF_B1S);
    float* b2s  = (float*)(smem + OFF_B2S);
    float* oacc = (float*)(smem + OFF_OACC);

    // prologue: whole-batch x into smem, biases, cu
    {
        const float4* src = (const float4*)(x + (size_t)b * NN * 3);
        float4* dst = (float4*)xall;
        #pragma unroll
        for (int m = 0; m < 3; m++) dst[tid + m * 256] = src[tid + m * 256];
    }
    if (tid < 128) {
        float s = b0[tid];
        #pragma unroll
        for (int g = 0; g < GG; g++) s += u[b * GG + g] * W0[g * HH + tid];
        cu[tid]  = s;
        w0n[tid] = W0[8 * HH + tid];
        b1s[tid] = b1[tid];
        b2s[tid] = b2[tid];
    }
    for (int t = tid; t < 384; t += 256) oacc[t] = 0.0f;
    __syncthreads();

    // Bj frag image: for jblock jb, lane ln: half2(X[col][2c], X[col][2c+1]), col=jb*8+(ln>>2)
    #pragma unroll
    for (int m = 0; m < 16; m++) {
        const int idx = tid + m * 256;            // 0..4095
        const int jb = idx >> 5, ln = idx & 31;
        const int c2 = (ln & 3) * 2, col = jb * 8 + (ln >> 2);
        const float v0 = (c2 < 3) ? xall[col * 3 + c2] : 0.0f;
        const float v1 = (c2 + 1 < 3) ? xall[col * 3 + c2 + 1] : 0.0f;
        *(unsigned*)(smem + OFF_BJ + idx * 4) = pack2(v0, v1);
    }
    if (tid < 128) {
        const float* y = xall + (size_t)(i0 + tid) * 3;
        nrm[tid] = asqrt(y[0] * y[0] + y[1] * y[1] + y[2] * y[2]);
    }
    __syncthreads();

    // Xi dot-A fragments (m16n8k8): fixed per warp
    unsigned xiA[2][2];
    {
        const int c2 = (lane & 3) * 2;
        #pragma unroll
        for (int m = 0; m < 2; m++) {
            const int r = rg * 32 + m * 16 + (lane >> 2);
            const float* ya = xall + (size_t)(i0 + r) * 3;
            const float* yb = xall + (size_t)(i0 + r + 8) * 3;
            const float a0 = (c2 < 3) ? ya[c2] : 0.0f;
            const float a1 = (c2 + 1 < 3) ? ya[c2 + 1] : 0.0f;
            const float c0 = (c2 < 3) ? yb[c2] : 0.0f;
            const float c1 = (c2 + 1 < 3) ? yb[c2 + 1] : 0.0f;
            xiA[m][0] = pack2(a0, a1);
            xiA[m][1] = pack2(c0, c1);
        }
    }

    // acc init with bias + u/norm features
    float acc[16][4];
    {
        const int cp = lane & 3, r8 = lane >> 2;
        #pragma unroll
        for (int m = 0; m < 2; m++) {
            const int r1 = rg * 32 + m * 16 + r8, r2 = r1 + 8;
            const float n1 = nrm[r1], n2 = nrm[r2];
            #pragma unroll
            for (int nfl = 0; nfl < 8; nfl++) {
                const int c = cg * 64 + nfl * 8 + cp * 2;
                float* A = acc[m * 8 + nfl];
                A[0] = cu[c]     + n1 * w0n[c];
                A[1] = cu[c + 1] + n1 * w0n[c + 1];
                A[2] = cu[c]     + n2 * w0n[c];
                A[3] = cu[c + 1] + n2 * w0n[c + 1];
            }
        }
    }

    auto copy16k = [&](const unsigned char* src, unsigned dst) {
        src += tid * 16; dst += tid * 16;
        #pragma unroll
        for (int m = 0; m < 4; m++) cpa16(dst + m * 4096, src + m * 4096);
    };
    const unsigned bufB[2] = { sb + OFF_B0, sb + OFF_B1 };

    // stage W0 chunk 0
    copy16k(gBd, bufB[0]);
    cpa_wait_all();
    __syncthreads();

    // ---------------- layer 0: A generated in-register via dot-MMAs ----------------
    const int kkl = lane & 15, kx = lane & 7, nfs = lane >> 4;
    const unsigned bjBase = sb + OFF_BJ + (unsigned)lane * 4;
    for (int cb = 0; cb < 16; cb++) {
        const int cur = cb & 1, nxt = cur ^ 1;
        if (cb < 15) copy16k(gBd + (cb + 1) * 16384, bufB[nxt]);
        else         copy16k(gW1, bufB[0]);   // B0 free: last read at cb=14

        const unsigned bjChunk = bjBase + (unsigned)cb * 1024;
        #pragma unroll
        for (int ks = 0; ks < 64; ks += 16) {
            // dot B frags (2 jblocks of 8)
            unsigned bj0, bj1;
            asm("ld.shared.b32 %0, [%1];" : "=r"(bj0) : "r"(bjChunk + (unsigned)(ks >> 3) * 128));
            asm("ld.shared.b32 %0, [%1];" : "=r"(bj1) : "r"(bjChunk + (unsigned)(ks >> 3) * 128 + 128));
            // dots: D[m][jb] (16x8 fp32 fragments)
            float d[4][4];
            #pragma unroll
            for (int q = 0; q < 4; q++) { d[q][0] = 0.f; d[q][1] = 0.f; d[q][2] = 0.f; d[q][3] = 0.f; }
            mma16808(d[0], xiA[0][0], xiA[0][1], bj0);
            mma16808(d[1], xiA[0][0], xiA[0][1], bj1);
            mma16808(d[2], xiA[1][0], xiA[1][1], bj0);
            mma16808(d[3], xiA[1][0], xiA[1][1], bj1);
            // sqrt + pack -> main A fragments (m16n8k16)
            unsigned af[2][4];
            #pragma unroll
            for (int m = 0; m < 2; m++) {
                af[m][0] = pack2(asqrt(d[2 * m][0]),     asqrt(d[2 * m][1]));
                af[m][1] = pack2(asqrt(d[2 * m][2]),     asqrt(d[2 * m][3]));
                af[m][2] = pack2(asqrt(d[2 * m + 1][0]), asqrt(d[2 * m + 1][1]));
                af[m][3] = pack2(asqrt(d[2 * m + 1][2]), asqrt(d[2 * m + 1][3]));
            }
            // main MMAs vs W0 chunk
            const unsigned bbase = bufB[cur] + (unsigned)(ks + kkl) * 256;
            #pragma unroll
            for (int h = 0; h < 2; h++) {
                unsigned bb[8];
                #pragma unroll
                for (int p = 0; p < 2; p++) {
                    const int nf = cg * 8 + h * 4 + p * 2 + nfs;
                    ldsm_x4t(bb + p * 4, bbase + ((unsigned)(nf ^ kx) << 4));
                }
                #pragma unroll
                for (int p = 0; p < 2; p++) {
                    #pragma unroll
                    for (int m = 0; m < 2; m++) {
                        mma16816(acc[m * 8 + h * 4 + p * 2 + 0], af[m], bb[p * 4 + 0], bb[p * 4 + 1]);
                        mma16816(acc[m * 8 + h * 4 + p * 2 + 1], af[m], bb[p * 4 + 2], bb[p * 4 + 3]);
                    }
                }
            }
        }
        cpa_wait_all();
        __syncthreads();
    }

    // ---------------- layer 0 epilogue -> H; layer 1 ----------------
    epi_split(acc, smem + OFF_H, b1s, rg, cg, lane);
    copy16k(gW1 + 16384, bufB[1]);
    cpa_wait_all();
    __syncthreads();

    mma_k64(acc, sb + OFF_H, bufB[0], 0, rg, cg, lane);
    mma_k64(acc, sb + OFF_H, bufB[1], 64, rg, cg, lane);
    __syncthreads();

    // ---------------- layer 1 epilogue -> H; layer 2 ----------------
    epi_split(acc, smem + OFF_H, b2s, rg, cg, lane);
    copy16k(gW2, bufB[0]);
    copy16k(gW2 + 16384, bufB[1]);
    cpa_wait_all();
    __syncthreads();

    mma_k64(acc, sb + OFF_H, bufB[0], 0, rg, cg, lane);
    mma_k64(acc, sb + OFF_H, bufB[1], 64, rg, cg, lane);

    // ---------------- final contraction ----------------
    {
        const int r8 = lane >> 2;
        #pragma unroll
        for (int m = 0; m < 2; m++) {
            const int r1 = rg * 32 + m * 16 + r8, r2 = r1 + 8;
            const float* ya = xall + (size_t)(i0 + r1) * 3;
            const float* yb = xall + (size_t)(i0 + r2) * 3;
            const float x10 = ya[0], x11 = ya[1], x12 = ya[2];
            const float x20 = yb[0], x21 = yb[1], x22 = yb[2];
            #pragma unroll
            for (int nfl = 0; nfl < 8; nfl++) {
                float* A = acc[m * 8 + nfl];
                float s[6];
                s[0] = A[0] * x10 + A[2] * x20;
                s[1] = A[0] * x11 + A[2] * x21;
                s[2] = A[0] * x12 + A[2] * x22;
                s[3] = A[1] * x10 + A[3] * x20;
                s[4] = A[1] * x11 + A[3] * x21;
                s[5] = A[1] * x12 + A[3] * x22;
                #pragma unroll
                for (int q = 0; q < 6; q++) {
                    s[q] += __shfl_xor_sync(0xffffffffu, s[q], 4);
                    s[q] += __shfl_xor_sync(0xffffffffu, s[q], 8);
                    s[q] += __shfl_xor_sync(0xffffffffu, s[q], 16);
                }
                if (lane < 4) {
                    const int c = cg * 64 + nfl * 8 + lane * 2;
                    atomicAdd(&oacc[c * 3 + 0], s[0]);
                    atomicAdd(&oacc[c * 3 + 1], s[1]);
                    atomicAdd(&oacc[c * 3 + 2], s[2]);
                    atomicAdd(&oacc[(c + 1) * 3 + 0], s[3]);
                    atomicAdd(&oacc[(c + 1) * 3 + 1], s[4]);
                    atomicAdd(&oacc[(c + 1) * 3 + 2], s[5]);
                }
            }
        }
    }
    __syncthreads();
    const float inv = 1.0f / (float)NN;
    for (int t = tid; t < 384; t += 256)
        atomicAdd(out + (size_t)b * 384 + t, oacc[t] * inv);
}

// ---------------------------------------------------------------------------
extern "C" void kernel_launch(void* const* d_in, const int* in_sizes, int n_in,
                              void* d_out, int out_size) {
    const float* x  = (const float*)d_in[0];
    const float* u  = (const float*)d_in[1];
    const float* W0 = (const float*)d_in[2];
    const float* b0 = (const float*)d_in[3];
    const float* W1 = (const float*)d_in[4];
    const float* b1 = (const float*)d_in[5];
    const float* W2 = (const float*)d_in[6];
    const float* b2 = (const float*)d_in[7];
    float* out = (float*)d_out;

    cudaFuncSetAttribute(k_main, cudaFuncAttributeMaxDynamicSharedMemorySize, SMEM_BYTES);

    k_prep<<<688, 256>>>(W0, W1, W2, out);
    k_main<<<BB * (NN / 128), 256, SMEM_BYTES>>>(x, u, W0, b0, b1, b2, out);
}

// round 10
// speedup vs baseline: 1.0849x; 1.0036x over previous
#include <cuda_runtime.h>
#include <cuda_fp16.h>

#define BB 32
#define NN 1024
#define GG 8
#define HH 128

// ---- prepped fp16 weight images, ldmatrix-swizzled k64 chunks ----
__device__ __align__(16) unsigned char gBd[16 * 16384];   // W0 rows 9..1032 (dots)
__device__ __align__(16) unsigned char gW1[2 * 16384];
__device__ __align__(16) unsigned char gW2[2 * 16384];

// ---- smem map (bytes) ----
#define OFF_BJ   0        // dot B-frag image: 128 jblocks x 128B = 16KB   [layer0]
#define OFF_H    0        // h plane (128x128 fp16, 256B rows) 32KB        [layer phase]
#define OFF_B0   32768    // W0 chunk buf0 / W chunk0
#define OFF_B1   49152    // W0 chunk buf1 / W chunk1
#define OFF_XALL 65536    // x[b] fp32 [1024][3] = 12288 B
#define OFF_NRM  77824
#define OFF_CU   78336
#define OFF_W0N  78848
#define OFF_B1S  79360
#define OFF_B2S  79872
#define OFF_OACC 80384    // fp32 [128][3]
#define SMEM_BYTES 81920

// ---------------- helpers ----------------
__device__ __forceinline__ unsigned smem_u32(const void* p) {
    unsigned a;
    asm("{ .reg .u64 t; cvta.to.shared.u64 t, %1; cvt.u32.u64 %0, t; }" : "=r"(a) : "l"(p));
    return a;
}
__device__ __forceinline__ void ldsm_x4(unsigned* r, unsigned a) {
    asm volatile("ldmatrix.sync.aligned.m8n8.x4.shared.b16 {%0,%1,%2,%3}, [%4];"
                 : "=r"(r[0]), "=r"(r[1]), "=r"(r[2]), "=r"(r[3]) : "r"(a));
}
__device__ __forceinline__ void ldsm_x4t(unsigned* r, unsigned a) {
    asm volatile("ldmatrix.sync.aligned.m8n8.x4.trans.shared.b16 {%0,%1,%2,%3}, [%4];"
                 : "=r"(r[0]), "=r"(r[1]), "=r"(r[2]), "=r"(r[3]) : "r"(a));
}
__device__ __forceinline__ void mma16816(float* d, const unsigned* a, unsigned b0, unsigned b1) {
    asm volatile(
        "mma.sync.aligned.m16n8k16.row.col.f32.f16.f16.f32 "
        "{%0,%1,%2,%3}, {%4,%5,%6,%7}, {%8,%9}, {%0,%1,%2,%3};"
        : "+f"(d[0]), "+f"(d[1]), "+f"(d[2]), "+f"(d[3])
        : "r"(a[0]), "r"(a[1]), "r"(a[2]), "r"(a[3]), "r"(b0), "r"(b1));
}
__device__ __forceinline__ void mma16808(float* d, unsigned a0, unsigned a1, unsigned b0) {
    asm volatile(
        "mma.sync.aligned.m16n8k8.row.col.f32.f16.f16.f32 "
        "{%0,%1,%2,%3}, {%4,%5}, {%6}, {%0,%1,%2,%3};"
        : "+f"(d[0]), "+f"(d[1]), "+f"(d[2]), "+f"(d[3])
        : "r"(a0), "r"(a1), "r"(b0));
}
__device__ __forceinline__ void cpa16(unsigned dst, const void* src) {
    asm volatile("cp.async.cg.shared.global [%0], [%1], 16;" :: "r"(dst), "l"(src));
}
__device__ __forceinline__ void cpa_wait_all() {
    asm volatile("cp.async.wait_all;" ::: "memory");
}
__device__ __forceinline__ float asqrt(float v) {   // MUFU.SQRT
    float r;
    asm("sqrt.approx.f32 %0, %1;" : "=f"(r) : "f"(v));
    return r;
}
__device__ __forceinline__ float leaky(float v) { return v > 0.0f ? v : 0.01f * v; }
__device__ __forceinline__ unsigned short h16(float v) {
    __half h = __float2half_rn(v);
    return *(unsigned short*)&h;
}
__device__ __forceinline__ unsigned pack2(float a, float b) {
    __half2 h = __floats2half2_rn(a, b);
    return *(unsigned*)&h;
}

// k64 MMA sweep for layers 1/2 (A from smem H plane).
__device__ __forceinline__ void mma_k64(float (&acc)[16][4], unsigned aBase, unsigned bBase,
                                        int kOff, int rg, int cg, int lane) {
    const int il  = lane & 15;
    const int kq  = lane >> 4;
    const int kkl = lane & 15;
    const int kx  = lane & 7;
    const int nfs = lane >> 4;
    #pragma unroll
    for (int ks = 0; ks < 64; ks += 16) {
        const int kc = ((kOff + ks) >> 3) + kq;
        unsigned a[2][4];
        #pragma unroll
        for (int m = 0; m < 2; m++) {
            const int i = rg * 32 + m * 16 + il;
            ldsm_x4(a[m], aBase + i * 256 + ((unsigned)(kc ^ (i & 7)) << 4));
        }
        const unsigned bbase = (unsigned)(ks + kkl) * 256;
        unsigned bb[16];
        #pragma unroll
        for (int p = 0; p < 4; p++) {
            const int nf = cg * 8 + p * 2 + nfs;
            ldsm_x4t(bb + p * 4, bBase + bbase + ((unsigned)(nf ^ kx) << 4));
        }
        #pragma unroll
        for (int p = 0; p < 4; p++) {
            #pragma unroll
            for (int m = 0; m < 2; m++) {
                mma16816(acc[m * 8 + p * 2 + 0], a[m], bb[p * 4 + 0], bb[p * 4 + 1]);
                mma16816(acc[m * 8 + p * 2 + 1], a[m], bb[p * 4 + 2], bb[p * 4 + 3]);
            }
        }
    }
}

// Epilogue: leaky + fp16 into h plane (256B rows), re-init acc with bias.
__device__ __forceinline__ void epi_split(float (&acc)[16][4], unsigned char* dH,
                                          const float* nb, int rg, int cg, int lane) {
    const int cp = lane & 3, r8 = lane >> 2;
    #pragma unroll
    for (int m = 0; m < 2; m++) {
        const int r1 = rg * 32 + m * 16 + r8, r2 = r1 + 8;
        #pragma unroll
        for (int nfl = 0; nfl < 8; nfl++) {
            float* A = acc[m * 8 + nfl];
            const int c = cg * 64 + nfl * 8 + cp * 2;
            unsigned short a0 = h16(leaky(A[0])), a1 = h16(leaky(A[1]));
            unsigned short a2 = h16(leaky(A[2])), a3 = h16(leaky(A[3]));
            const unsigned o1 = r1 * 256 + ((unsigned)(((c >> 3) ^ (r1 & 7))) << 4) + (c & 7) * 2;
            const unsigned o2 = r2 * 256 + ((unsigned)(((c >> 3) ^ (r2 & 7))) << 4) + (c & 7) * 2;
            *(unsigned*)(dH + o1) = (unsigned)a0 | ((unsigned)a1 << 16);
            *(unsigned*)(dH + o2) = (unsigned)a2 | ((unsigned)a3 << 16);
            A[0] = nb[c]; A[1] = nb[c + 1]; A[2] = nb[c]; A[3] = nb[c + 1];
        }
    }
}

// ---------------------------------------------------------------------------
// Prep (+ output zero): round weights to fp16 into swizzled chunk images.
__global__ void k_prep(const float* __restrict__ W0, const float* __restrict__ W1,
                       const float* __restrict__ W2, float* __restrict__ out) {
    int idx = blockIdx.x * 256 + threadIdx.x;
    float v; unsigned char* dp;
    int k, n;
    if (idx < 131072) {
        k = idx >> 7; n = idx & 127;
        v = W0[(9 + k) * HH + n];
        dp = gBd;
    } else if (idx < 147456) {
        int t = idx - 131072;
        k = t >> 7; n = t & 127;
        v = W1[k * HH + n];
        dp = gW1;
    } else if (idx < 163840) {
        int t = idx - 147456;
        k = t >> 7; n = t & 127;
        v = W2[k * HH + n];
        dp = gW2;
    } else {
        int t = idx - 163840;
        if (t < BB * HH * 3) out[t] = 0.0f;
        return;
    }
    const int cb = k >> 6, kl = k & 63;
    const unsigned off = cb * 16384 + kl * 256 + ((((n >> 3) ^ (kl & 7))) << 4) + (n & 7) * 2;
    *(unsigned short*)(dp + off) = h16(v);
}

// ---------------------------------------------------------------------------
__global__ void __launch_bounds__(256, 2)
k_main(const float* __restrict__ x, const float* __restrict__ u,
       const float* __restrict__ W0, const float* __restrict__ b0,
       const float* __restrict__ b1, const float* __restrict__ b2,
       float* __restrict__ out)
{
    extern __shared__ __align__(1024) unsigned char smem[];
    const unsigned sb = smem_u32(smem);
    const int tid = threadIdx.x, w = tid >> 5, lane = tid & 31;
    const int rg = w & 3, cg = w >> 2;
    const int b = blockIdx.x >> 3, i0 = (blockIdx.x & 7) * 128;

    float* xall = (float*)(smem + OFF_XALL);
    float* nrm  = (float*)(smem + OFF_NRM);
    float* cu   = (float*)(smem + OFF_CU);
    float* w0n  = (float*)(smem + OFF_W0N);
    float* b1s  = (float*)(smem + OFF_B1S);
    float* b2s  = (float*)(smem + OFF_B2S);
    float* oacc = (float*)(smem + OFF_OACC);

    // prologue: whole-batch x into smem, biases, cu
    {
        const float4* src = (const float4*)(x + (size_t)b * NN * 3);
        float4* dst = (float4*)xall;
        #pragma unroll
        for (int m = 0; m < 3; m++) dst[tid + m * 256] = src[tid + m * 256];
    }
    if (tid < 128) {
        float s = b0[tid];
        #pragma unroll
        for (int g = 0; g < GG; g++) s += u[b * GG + g] * W0[g * HH + tid];
        cu[tid]  = s;
        w0n[tid] = W0[8 * HH + tid];
        b1s[tid] = b1[tid];
        b2s[tid] = b2[tid];
    }
    for (int t = tid; t < 384; t += 256) oacc[t] = 0.0f;
    __syncthreads();

    // Bj frag image: for jblock jb, lane ln: half2(X[col][2c], X[col][2c+1]), col=jb*8+(ln>>2)
    #pragma unroll
    for (int m = 0; m < 16; m++) {
        const int idx = tid + m * 256;            // 0..4095
        const int jb = idx >> 5, ln = idx & 31;
        const int c2 = (ln & 3) * 2, col = jb * 8 + (ln >> 2);
        const float v0 = (c2 < 3) ? xall[col * 3 + c2] : 0.0f;
        const float v1 = (c2 + 1 < 3) ? xall[col * 3 + c2 + 1] : 0.0f;
        *(unsigned*)(smem + OFF_BJ + idx * 4) = pack2(v0, v1);
    }
    if (tid < 128) {
        const float* y = xall + (size_t)(i0 + tid) * 3;
        nrm[tid] = asqrt(y[0] * y[0] + y[1] * y[1] + y[2] * y[2]);
    }
    __syncthreads();

    // Xi dot-A fragments (m16n8k8): fixed per warp
    unsigned xiA[2][2];
    {
        const int c2 = (lane & 3) * 2;
        #pragma unroll
        for (int m = 0; m < 2; m++) {
            const int r = rg * 32 + m * 16 + (lane >> 2);
            const float* ya = xall + (size_t)(i0 + r) * 3;
            const float* yb = xall + (size_t)(i0 + r + 8) * 3;
            const float a0 = (c2 < 3) ? ya[c2] : 0.0f;
            const float a1 = (c2 + 1 < 3) ? ya[c2 + 1] : 0.0f;
            const float c0 = (c2 < 3) ? yb[c2] : 0.0f;
            const float c1 = (c2 + 1 < 3) ? yb[c2 + 1] : 0.0f;
            xiA[m][0] = pack2(a0, a1);
            xiA[m][1] = pack2(c0, c1);
        }
    }

    // acc init with bias + u/norm features
    float acc[16][4];
    {
        const int cp = lane & 3, r8 = lane >> 2;
        #pragma unroll
        for (int m = 0; m < 2; m++) {
            const int r1 = rg * 32 + m * 16 + r8, r2 = r1 + 8;
            const float n1 = nrm[r1], n2 = nrm[r2];
            #pragma unroll
            for (int nfl = 0; nfl < 8; nfl++) {
                const int c = cg * 64 + nfl * 8 + cp * 2;
                float* A = acc[m * 8 + nfl];
                A[0] = cu[c]     + n1 * w0n[c];
                A[1] = cu[c + 1] + n1 * w0n[c + 1];
                A[2] = cu[c]     + n2 * w0n[c];
                A[3] = cu[c + 1] + n2 * w0n[c + 1];
            }
        }
    }

    auto copy16k = [&](const unsigned char* src, unsigned dst) {
        src += tid * 16; dst += tid * 16;
        #pragma unroll
        for (int m = 0; m < 4; m++) cpa16(dst + m * 4096, src + m * 4096);
    };
    const unsigned bufB[2] = { sb + OFF_B0, sb + OFF_B1 };

    // stage W0 chunk 0
    copy16k(gBd, bufB[0]);
    cpa_wait_all();
    __syncthreads();

    // ---------------- layer 0: A generated in-register via dot-MMAs ----------------
    const int kkl = lane & 15, kx = lane & 7, nfs = lane >> 4;
    const unsigned bjBase = sb + OFF_BJ + (unsigned)lane * 4;
    for (int cb = 0; cb < 16; cb++) {
        const int cur = cb & 1, nxt = cur ^ 1;
        if (cb < 15) copy16k(gBd + (cb + 1) * 16384, bufB[nxt]);
        else         copy16k(gW1, bufB[0]);   // B0 free: last read at cb=14

        const unsigned bjChunk = bjBase + (unsigned)cb * 1024;
        #pragma unroll
        for (int ks = 0; ks < 64; ks += 16) {
            // dot B frags (2 jblocks of 8)
            unsigned bj0, bj1;
            asm("ld.shared.b32 %0, [%1];" : "=r"(bj0) : "r"(bjChunk + (unsigned)(ks >> 3) * 128));
            asm("ld.shared.b32 %0, [%1];" : "=r"(bj1) : "r"(bjChunk + (unsigned)(ks >> 3) * 128 + 128));
            // dots: D[m][jb] (16x8 fp32 fragments)
            float d[4][4];
            #pragma unroll
            for (int q = 0; q < 4; q++) { d[q][0] = 0.f; d[q][1] = 0.f; d[q][2] = 0.f; d[q][3] = 0.f; }
            mma16808(d[0], xiA[0][0], xiA[0][1], bj0);
            mma16808(d[1], xiA[0][0], xiA[0][1], bj1);
            mma16808(d[2], xiA[1][0], xiA[1][1], bj0);
            mma16808(d[3], xiA[1][0], xiA[1][1], bj1);
            // sqrt + pack -> main A fragments (m16n8k16)
            unsigned af[2][4];
            #pragma unroll
            for (int m = 0; m < 2; m++) {
                af[m][0] = pack2(asqrt(d[2 * m][0]),     asqrt(d[2 * m][1]));
                af[m][1] = pack2(asqrt(d[2 * m][2]),     asqrt(d[2 * m][3]));
                af[m][2] = pack2(asqrt(d[2 * m + 1][0]), asqrt(d[2 * m + 1][1]));
                af[m][3] = pack2(asqrt(d[2 * m + 1][2]), asqrt(d[2 * m + 1][3]));
            }
            // main MMAs vs W0 chunk
            const unsigned bbase = bufB[cur] + (unsigned)(ks + kkl) * 256;
            #pragma unroll
            for (int h = 0; h < 2; h++) {
                unsigned bb[8];
                #pragma unroll
                for (int p = 0; p < 2; p++) {
                    const int nf = cg * 8 + h * 4 + p * 2 + nfs;
                    ldsm_x4t(bb + p * 4, bbase + ((unsigned)(nf ^ kx) << 4));
                }
                #pragma unroll
                for (int p = 0; p < 2; p++) {
                    #pragma unroll
                    for (int m = 0; m < 2; m++) {
                        mma16816(acc[m * 8 + h * 4 + p * 2 + 0], af[m], bb[p * 4 + 0], bb[p * 4 + 1]);
                        mma16816(acc[m * 8 + h * 4 + p * 2 + 1], af[m], bb[p * 4 + 2], bb[p * 4 + 3]);
                    }
                }
            }
        }
        cpa_wait_all();
        __syncthreads();
    }

    // ---------------- layer 0 epilogue -> H; layer 1 ----------------
    epi_split(acc, smem + OFF_H, b1s, rg, cg, lane);
    copy16k(gW1 + 16384, bufB[1]);
    cpa_wait_all();
    __syncthreads();

    mma_k64(acc, sb + OFF_H, bufB[0], 0, rg, cg, lane);
    mma_k64(acc, sb + OFF_H, bufB[1], 64, rg, cg, lane);
    __syncthreads();

    // ---------------- layer 1 epilogue -> H; layer 2 ----------------
    epi_split(acc, smem + OFF_H, b2s, rg, cg, lane);
    copy16k(gW2, bufB[0]);
    copy16k(gW2 + 16384, bufB[1]);
    cpa_wait_all();
    __syncthreads();

    mma_k64(acc, sb + OFF_H, bufB[0], 0, rg, cg, lane);
    mma_k64(acc, sb + OFF_H, bufB[1], 64, rg, cg, lane);

    // ---------------- final contraction ----------------
    {
        const int r8 = lane >> 2;
        #pragma unroll
        for (int m = 0; m < 2; m++) {
            const int r1 = rg * 32 + m * 16 + r8, r2 = r1 + 8;
            const float* ya = xall + (size_t)(i0 + r1) * 3;
            const float* yb = xall + (size_t)(i0 + r2) * 3;
            const float x10 = ya[0], x11 = ya[1], x12 = ya[2];
            const float x20 = yb[0], x21 = yb[1], x22 = yb[2];
            #pragma unroll
            for (int nfl = 0; nfl < 8; nfl++) {
                float* A = acc[m * 8 + nfl];
                float s[6];
                s[0] = A[0] * x10 + A[2] * x20;
                s[1] = A[0] * x11 + A[2] * x21;
                s[2] = A[0] * x12 + A[2] * x22;
                s[3] = A[1] * x10 + A[3] * x20;
                s[4] = A[1] * x11 + A[3] * x21;
                s[5] = A[1] * x12 + A[3] * x22;
                #pragma unroll
                for (int q = 0; q < 6; q++) {
                    s[q] += __shfl_xor_sync(0xffffffffu, s[q], 4);
                    s[q] += __shfl_xor_sync(0xffffffffu, s[q], 8);
                    s[q] += __shfl_xor_sync(0xffffffffu, s[q], 16);
                }
                if (lane < 4) {
                    const int c = cg * 64 + nfl * 8 + lane * 2;
                    atomicAdd(&oacc[c * 3 + 0], s[0]);
                    atomicAdd(&oacc[c * 3 + 1], s[1]);
                    atomicAdd(&oacc[c * 3 + 2], s[2]);
                    atomicAdd(&oacc[(c + 1) * 3 + 0], s[3]);
                    atomicAdd(&oacc[(c + 1) * 3 + 1], s[4]);
                    atomicAdd(&oacc[(c + 1) * 3 + 2], s[5]);
                }
            }
        }
    }
    __syncthreads();
    const float inv = 1.0f / (float)NN;
    for (int t = tid; t < 384; t += 256)
        atomicAdd(out + (size_t)b * 384 + t, oacc[t] * inv);
}

// ---------------------------------------------------------------------------
extern "C" void kernel_launch(void* const* d_in, const int* in_sizes, int n_in,
                              void* d_out, int out_size) {
    const float* x  = (const float*)d_in[0];
    const float* u  = (const float*)d_in[1];
    const float* W0 = (const float*)d_in[2];
    const float* b0 = (const float*)d_in[3];
    const float* W1 = (const float*)d_in[4];
    const float* b1 = (const float*)d_in[5];
    const float* W2 = (const float*)d_in[6];
    const float* b2 = (const float*)d_in[7];
    float* out = (float*)d_out;

    cudaFuncSetAttribute(k_main, cudaFuncAttributeMaxDynamicSharedMemorySize, SMEM_BYTES);

    k_prep<<<688, 256>>>(W0, W1, W2, out);
    k_main<<<BB * (NN / 128), 256, SMEM_BYTES>>>(x, u, W0, b0, b1, b2, out);
}

// round 11
// speedup vs baseline: 1.1273x; 1.0391x over previous
#include <cuda_runtime.h>
#include <cuda_fp16.h>

#define BB 32
#define NN 1024
#define GG 8
#define HH 128

// ---- prepped B operands in EXACT mma fragment order ----
// entry (ck, nfp, lane) = 16B = {b0(nf0), b1(nf0), b0(nf0+1), b1(nf0+1)},
// nf0 = 2*nfp; b0 lane l = {B[ck*16+2*(l&3)][c], B[..+1][c]}, c = nfp*16+(l>>2); b1: k+8.
__device__ __align__(16) unsigned gBf[65536];   // W0 dots rows: 64 ck x 8 nfp x 32 x 4w (256KB)
__device__ __align__(16) unsigned gW1f[8192];   // 8 ck x 8 nfp x 32 x 4w (32KB)
__device__ __align__(16) unsigned gW2f[8192];

// ---- smem map (bytes) ----
#define OFF_BJ   0        // dot B-frag image 16KB (layer0; overlaps H)
#define OFF_H    0        // h plane (128x128 fp16, 256B rows) 32KB (layer phase)
#define OFF_XALL 32768    // x[b] fp32 [1024][3]
#define OFF_NRM  45056
#define OFF_CU   45568
#define OFF_W0N  46080
#define OFF_B1S  46592
#define OFF_B2S  47104
#define OFF_OACC 47616    // fp32 [128][3]
#define SMEM_BYTES 49152

// ---------------- helpers ----------------
__device__ __forceinline__ unsigned smem_u32(const void* p) {
    unsigned a;
    asm("{ .reg .u64 t; cvta.to.shared.u64 t, %1; cvt.u32.u64 %0, t; }" : "=r"(a) : "l"(p));
    return a;
}
__device__ __forceinline__ void ldsm_x4(unsigned* r, unsigned a) {
    asm volatile("ldmatrix.sync.aligned.m8n8.x4.shared.b16 {%0,%1,%2,%3}, [%4];"
                 : "=r"(r[0]), "=r"(r[1]), "=r"(r[2]), "=r"(r[3]) : "r"(a));
}
__device__ __forceinline__ void mma16816(float* d, const unsigned* a, unsigned b0, unsigned b1) {
    asm volatile(
        "mma.sync.aligned.m16n8k16.row.col.f32.f16.f16.f32 "
        "{%0,%1,%2,%3}, {%4,%5,%6,%7}, {%8,%9}, {%0,%1,%2,%3};"
        : "+f"(d[0]), "+f"(d[1]), "+f"(d[2]), "+f"(d[3])
        : "r"(a[0]), "r"(a[1]), "r"(a[2]), "r"(a[3]), "r"(b0), "r"(b1));
}
__device__ __forceinline__ void mma16808(float* d, unsigned a0, unsigned a1, unsigned b0) {
    asm volatile(
        "mma.sync.aligned.m16n8k8.row.col.f32.f16.f16.f32 "
        "{%0,%1,%2,%3}, {%4,%5}, {%6}, {%0,%1,%2,%3};"
        : "+f"(d[0]), "+f"(d[1]), "+f"(d[2]), "+f"(d[3])
        : "r"(a0), "r"(a1), "r"(b0));
}
__device__ __forceinline__ float asqrt(float v) {
    float r;
    asm("sqrt.approx.f32 %0, %1;" : "=f"(r) : "f"(v));
    return r;
}
__device__ __forceinline__ float leaky(float v) { return v > 0.0f ? v : 0.01f * v; }
__device__ __forceinline__ unsigned short h16(float v) {
    __half h = __float2half_rn(v);
    return *(unsigned short*)&h;
}
__device__ __forceinline__ unsigned pack2(float a, float b) {
    __half2 h = __floats2half2_rn(a, b);
    return *(unsigned*)&h;
}

// Epilogue: leaky + fp16 into h plane (256B rows), re-init acc with bias.
__device__ __forceinline__ void epi_split(float (&acc)[16][4], unsigned char* dH,
                                          const float* nb, int rg, int cg, int lane) {
    const int cp = lane & 3, r8 = lane >> 2;
    #pragma unroll
    for (int m = 0; m < 2; m++) {
        const int r1 = rg * 32 + m * 16 + r8, r2 = r1 + 8;
        #pragma unroll
        for (int nfl = 0; nfl < 8; nfl++) {
            float* A = acc[m * 8 + nfl];
            const int c = cg * 64 + nfl * 8 + cp * 2;
            unsigned short a0 = h16(leaky(A[0])), a1 = h16(leaky(A[1]));
            unsigned short a2 = h16(leaky(A[2])), a3 = h16(leaky(A[3]));
            const unsigned o1 = r1 * 256 + ((unsigned)(((c >> 3) ^ (r1 & 7))) << 4) + (c & 7) * 2;
            const unsigned o2 = r2 * 256 + ((unsigned)(((c >> 3) ^ (r2 & 7))) << 4) + (c & 7) * 2;
            *(unsigned*)(dH + o1) = (unsigned)a0 | ((unsigned)a1 << 16);
            *(unsigned*)(dH + o2) = (unsigned)a2 | ((unsigned)a3 << 16);
            A[0] = nb[c]; A[1] = nb[c + 1]; A[2] = nb[c]; A[3] = nb[c + 1];
        }
    }
}

// ---------------------------------------------------------------------------
// Prep (+ output zero): rewrite weights into mma B-fragment order.
__global__ void k_prep(const float* __restrict__ W0, const float* __restrict__ W1,
                       const float* __restrict__ W2, float* __restrict__ out) {
    const int idx = blockIdx.x * 256 + threadIdx.x;
    const float* src; unsigned* dst; int t;
    if (idx < 65536)      { src = W0 + 9 * HH; dst = gBf;  t = idx; }
    else if (idx < 73728) { src = W1;          dst = gW1f; t = idx - 65536; }
    else if (idx < 81920) { src = W2;          dst = gW2f; t = idx - 73728; }
    else {
        int z = idx - 81920;
        if (z < BB * HH * 3) out[z] = 0.0f;
        return;
    }
    const int e = t >> 2, wsel = t & 3;
    const int ck = e >> 8, nfp = (e >> 5) & 7, l = e & 31;
    const int k0  = ck * 16 + 2 * (l & 3) + ((wsel & 1) ? 8 : 0);
    const int col = nfp * 16 + ((wsel >> 1) ? 8 : 0) + (l >> 2);
    const float v0 = src[(size_t)k0 * HH + col];
    const float v1 = src[(size_t)(k0 + 1) * HH + col];
    dst[t] = (unsigned)h16(v0) | ((unsigned)h16(v1) << 16);
}

// ---------------------------------------------------------------------------
__global__ void __launch_bounds__(256, 2)
k_main(const float* __restrict__ x, const float* __restrict__ u,
       const float* __restrict__ W0, const float* __restrict__ b0,
       const float* __restrict__ b1, const float* __restrict__ b2,
       float* __restrict__ out)
{
    extern __shared__ __align__(1024) unsigned char smem[];
    const unsigned sb = smem_u32(smem);
    const int tid = threadIdx.x, w = tid >> 5, lane = tid & 31;
    const int rg = w & 3, cg = w >> 2;
    const int b = blockIdx.x >> 3, i0 = (blockIdx.x & 7) * 128;
    const int il = lane & 15, kq = lane >> 4;

    float* xall = (float*)(smem + OFF_XALL);
    float* nrm  = (float*)(smem + OFF_NRM);
    float* cu   = (float*)(smem + OFF_CU);
    float* w0n  = (float*)(smem + OFF_W0N);
    float* b1s  = (float*)(smem + OFF_B1S);
    float* b2s  = (float*)(smem + OFF_B2S);
    float* oacc = (float*)(smem + OFF_OACC);

    // prologue: whole-batch x into smem, biases, cu
    {
        const float4* src = (const float4*)(x + (size_t)b * NN * 3);
        float4* dst = (float4*)xall;
        #pragma unroll
        for (int m = 0; m < 3; m++) dst[tid + m * 256] = src[tid + m * 256];
    }
    if (tid < 128) {
        float s = b0[tid];
        #pragma unroll
        for (int g = 0; g < GG; g++) s += u[b * GG + g] * W0[g * HH + tid];
        cu[tid]  = s;
        w0n[tid] = W0[8 * HH + tid];
        b1s[tid] = b1[tid];
        b2s[tid] = b2[tid];
    }
    for (int t = tid; t < 384; t += 256) oacc[t] = 0.0f;
    __syncthreads();

    // Bj frag image (dot MMA B operands): jblock jb, lane ln -> half2 of X coords
    #pragma unroll
    for (int m = 0; m < 16; m++) {
        const int idx = tid + m * 256;            // 0..4095
        const int jb = idx >> 5, ln = idx & 31;
        const int c2 = (ln & 3) * 2, col = jb * 8 + (ln >> 2);
        const float v0 = (c2 < 3) ? xall[col * 3 + c2] : 0.0f;
        const float v1 = (c2 + 1 < 3) ? xall[col * 3 + c2 + 1] : 0.0f;
        *(unsigned*)(smem + OFF_BJ + idx * 4) = pack2(v0, v1);
    }
    if (tid < 128) {
        const float* y = xall + (size_t)(i0 + tid) * 3;
        nrm[tid] = asqrt(y[0] * y[0] + y[1] * y[1] + y[2] * y[2]);
    }
    __syncthreads();

    // Xi dot-A fragments (m16n8k8)
    unsigned xiA[2][2];
    {
        const int c2 = (lane & 3) * 2;
        #pragma unroll
        for (int m = 0; m < 2; m++) {
            const int r = rg * 32 + m * 16 + (lane >> 2);
            const float* ya = xall + (size_t)(i0 + r) * 3;
            const float* yb = xall + (size_t)(i0 + r + 8) * 3;
            const float a0 = (c2 < 3) ? ya[c2] : 0.0f;
            const float a1 = (c2 + 1 < 3) ? ya[c2 + 1] : 0.0f;
            const float c0 = (c2 < 3) ? yb[c2] : 0.0f;
            const float c1 = (c2 + 1 < 3) ? yb[c2 + 1] : 0.0f;
            xiA[m][0] = pack2(a0, a1);
            xiA[m][1] = pack2(c0, c1);
        }
    }

    // acc init with bias + u/norm features
    float acc[16][4];
    {
        const int cp = lane & 3, r8 = lane >> 2;
        #pragma unroll
        for (int m = 0; m < 2; m++) {
            const int r1 = rg * 32 + m * 16 + r8, r2 = r1 + 8;
            const float n1 = nrm[r1], n2 = nrm[r2];
            #pragma unroll
            for (int nfl = 0; nfl < 8; nfl++) {
                const int c = cg * 64 + nfl * 8 + cp * 2;
                float* A = acc[m * 8 + nfl];
                A[0] = cu[c]     + n1 * w0n[c];
                A[1] = cu[c + 1] + n1 * w0n[c + 1];
                A[2] = cu[c]     + n2 * w0n[c];
                A[3] = cu[c + 1] + n2 * w0n[c + 1];
            }
        }
    }

    // ---------------- layer 0: BARRIER-FREE (B fragments via LDG, A via dot-MMAs) ----
    const unsigned bjBase = sb + OFF_BJ + (unsigned)lane * 4;
    const uint4* Bf = (const uint4*)gBf;
    for (int cb = 0; cb < 16; cb++) {
        const unsigned bjChunk = bjBase + (unsigned)cb * 1024;
        #pragma unroll
        for (int ks16 = 0; ks16 < 4; ks16++) {
            // B fragments for this warp's 8 nf (4 x 512B-strided LDG.128)
            const uint4* bp = Bf + (size_t)(((cb * 4 + ks16) * 8 + cg * 4) * 32 + lane);
            const uint4 q0 = __ldg(bp);
            const uint4 q1 = __ldg(bp + 32);
            const uint4 q2 = __ldg(bp + 64);
            const uint4 q3 = __ldg(bp + 96);
            // dot B frags (2 jblocks of 8)
            unsigned bj0, bj1;
            asm("ld.shared.b32 %0, [%1];" : "=r"(bj0) : "r"(bjChunk + (unsigned)ks16 * 256));
            asm("ld.shared.b32 %0, [%1];" : "=r"(bj1) : "r"(bjChunk + (unsigned)ks16 * 256 + 128));
            // dots
            float d[4][4];
            #pragma unroll
            for (int q = 0; q < 4; q++) { d[q][0] = 0.f; d[q][1] = 0.f; d[q][2] = 0.f; d[q][3] = 0.f; }
            mma16808(d[0], xiA[0][0], xiA[0][1], bj0);
            mma16808(d[1], xiA[0][0], xiA[0][1], bj1);
            mma16808(d[2], xiA[1][0], xiA[1][1], bj0);
            mma16808(d[3], xiA[1][0], xiA[1][1], bj1);
            // sqrt + pack -> A fragments
            unsigned af[2][4];
            #pragma unroll
            for (int m = 0; m < 2; m++) {
                af[m][0] = pack2(asqrt(d[2 * m][0]),     asqrt(d[2 * m][1]));
                af[m][1] = pack2(asqrt(d[2 * m][2]),     asqrt(d[2 * m][3]));
                af[m][2] = pack2(asqrt(d[2 * m + 1][0]), asqrt(d[2 * m + 1][1]));
                af[m][3] = pack2(asqrt(d[2 * m + 1][2]), asqrt(d[2 * m + 1][3]));
            }
            // main MMAs
            #pragma unroll
            for (int m = 0; m < 2; m++) {
                mma16816(acc[m * 8 + 0], af[m], q0.x, q0.y);
                mma16816(acc[m * 8 + 1], af[m], q0.z, q0.w);
                mma16816(acc[m * 8 + 2], af[m], q1.x, q1.y);
                mma16816(acc[m * 8 + 3], af[m], q1.z, q1.w);
                mma16816(acc[m * 8 + 4], af[m], q2.x, q2.y);
                mma16816(acc[m * 8 + 5], af[m], q2.z, q2.w);
                mma16816(acc[m * 8 + 6], af[m], q3.x, q3.y);
                mma16816(acc[m * 8 + 7], af[m], q3.z, q3.w);
            }
        }
    }
    __syncthreads();   // all warps done reading Bj before H overwrites it

    // layer MMA: A from smem H (ldsm), B fragments via LDG
    auto layer_mma = [&](const uint4* Wf) {
        #pragma unroll
        for (int kt = 0; kt < 8; kt++) {
            const uint4* bp = Wf + (size_t)((kt * 8 + cg * 4) * 32 + lane);
            const uint4 q0 = __ldg(bp);
            const uint4 q1 = __ldg(bp + 32);
            const uint4 q2 = __ldg(bp + 64);
            const uint4 q3 = __ldg(bp + 96);
            unsigned a[2][4];
            const int kc = kt * 2 + kq;
            #pragma unroll
            for (int m = 0; m < 2; m++) {
                const int i = rg * 32 + m * 16 + il;
                ldsm_x4(a[m], sb + OFF_H + i * 256 + ((unsigned)(kc ^ (i & 7)) << 4));
            }
            #pragma unroll
            for (int m = 0; m < 2; m++) {
                mma16816(acc[m * 8 + 0], a[m], q0.x, q0.y);
                mma16816(acc[m * 8 + 1], a[m], q0.z, q0.w);
                mma16816(acc[m * 8 + 2], a[m], q1.x, q1.y);
                mma16816(acc[m * 8 + 3], a[m], q1.z, q1.w);
                mma16816(acc[m * 8 + 4], a[m], q2.x, q2.y);
                mma16816(acc[m * 8 + 5], a[m], q2.z, q2.w);
                mma16816(acc[m * 8 + 6], a[m], q3.x, q3.y);
                mma16816(acc[m * 8 + 7], a[m], q3.z, q3.w);
            }
        }
    };

    // ---------------- layer 0 epilogue -> H; layer 1 ----------------
    epi_split(acc, smem + OFF_H, b1s, rg, cg, lane);
    __syncthreads();
    layer_mma((const uint4*)gW1f);
    __syncthreads();

    // ---------------- layer 1 epilogue -> H; layer 2 ----------------
    epi_split(acc, smem + OFF_H, b2s, rg, cg, lane);
    __syncthreads();
    layer_mma((const uint4*)gW2f);

    // ---------------- final contraction ----------------
    {
        const int r8 = lane >> 2;
        #pragma unroll
        for (int m = 0; m < 2; m++) {
            const int r1 = rg * 32 + m * 16 + r8, r2 = r1 + 8;
            const float* ya = xall + (size_t)(i0 + r1) * 3;
            const float* yb = xall + (size_t)(i0 + r2) * 3;
            const float x10 = ya[0], x11 = ya[1], x12 = ya[2];
            const float x20 = yb[0], x21 = yb[1], x22 = yb[2];
            #pragma unroll
            for (int nfl = 0; nfl < 8; nfl++) {
                float* A = acc[m * 8 + nfl];
                float s[6];
                s[0] = A[0] * x10 + A[2] * x20;
                s[1] = A[0] * x11 + A[2] * x21;
                s[2] = A[0] * x12 + A[2] * x22;
                s[3] = A[1] * x10 + A[3] * x20;
                s[4] = A[1] * x11 + A[3] * x21;
                s[5] = A[1] * x12 + A[3] * x22;
                #pragma unroll
                for (int q = 0; q < 6; q++) {
                    s[q] += __shfl_xor_sync(0xffffffffu, s[q], 4);
                    s[q] += __shfl_xor_sync(0xffffffffu, s[q], 8);
                    s[q] += __shfl_xor_sync(0xffffffffu, s[q], 16);
                }
                if (lane < 4) {
                    const int c = cg * 64 + nfl * 8 + lane * 2;
                    atomicAdd(&oacc[c * 3 + 0], s[0]);
                    atomicAdd(&oacc[c * 3 + 1], s[1]);
                    atomicAdd(&oacc[c * 3 + 2], s[2]);
                    atomicAdd(&oacc[(c + 1) * 3 + 0], s[3]);
                    atomicAdd(&oacc[(c + 1) * 3 + 1], s[4]);
                    atomicAdd(&oacc[(c + 1) * 3 + 2], s[5]);
                }
            }
        }
    }
    __syncthreads();
    const float inv = 1.0f / (float)NN;
    for (int t = tid; t < 384; t += 256)
        atomicAdd(out + (size_t)b * 384 + t, oacc[t] * inv);
}

// ---------------------------------------------------------------------------
extern "C" void kernel_launch(void* const* d_in, const int* in_sizes, int n_in,
                              void* d_out, int out_size) {
    const float* x  = (const float*)d_in[0];
    const float* u  = (const float*)d_in[1];
    const float* W0 = (const float*)d_in[2];
    const float* b0 = (const float*)d_in[3];
    const float* W1 = (const float*)d_in[4];
    const float* b1 = (const float*)d_in[5];
    const float* W2 = (const float*)d_in[6];
    const float* b2 = (const float*)d_in[7];
    float* out = (float*)d_out;

    cudaFuncSetAttribute(k_main, cudaFuncAttributeMaxDynamicSharedMemorySize, SMEM_BYTES);

    k_prep<<<368, 256>>>(W0, W1, W2, out);
    k_main<<<BB * (NN / 128), 256, SMEM_BYTES>>>(x, u, W0, b0, b1, b2, out);
}

// round 12
// speedup vs baseline: 1.2500x; 1.1088x over previous
#include <cuda_runtime.h>
#include <cuda_fp16.h>

#define BB 32
#define NN 1024
#define GG 8
#define HH 128

// ---- prepped B operands in EXACT mma fragment order ----
// entry (ck, nfp, lane) = 16B = {b0(nf0), b1(nf0), b0(nf0+1), b1(nf0+1)},
// nf0 = 2*nfp; b0 lane l = {B[ck*16+2*(l&3)][c], B[..+1][c]}, c = nfp*16+(l>>2); b1: k+8.
__device__ __align__(16) unsigned gBf[65536];   // W0 dots rows: 64 ck x 8 nfp x 32 x 4w (256KB)
__device__ __align__(16) unsigned gW1f[8192];   // 8 ck x 8 nfp x 32 x 4w (32KB)
__device__ __align__(16) unsigned gW2f[8192];

// ---- smem map (bytes) ----
#define OFF_BJ   0        // dot B-frag image 16KB (layer0; overlaps H)
#define OFF_H    0        // h plane (128x128 fp16, 256B rows) 32KB (layer phase)
#define OFF_XALL 32768    // x[b] fp32 [1024][3]
#define OFF_NRM  45056
#define OFF_CU   45568
#define OFF_W0N  46080
#define OFF_B1S  46592
#define OFF_B2S  47104
#define OFF_OACC 47616    // fp32 [128][3]
#define SMEM_BYTES 49152

// ---------------- helpers ----------------
__device__ __forceinline__ unsigned smem_u32(const void* p) {
    unsigned a;
    asm("{ .reg .u64 t; cvta.to.shared.u64 t, %1; cvt.u32.u64 %0, t; }" : "=r"(a) : "l"(p));
    return a;
}
__device__ __forceinline__ void ldsm_x4(unsigned* r, unsigned a) {
    asm volatile("ldmatrix.sync.aligned.m8n8.x4.shared.b16 {%0,%1,%2,%3}, [%4];"
                 : "=r"(r[0]), "=r"(r[1]), "=r"(r[2]), "=r"(r[3]) : "r"(a));
}
__device__ __forceinline__ void mma16816(float* d, const unsigned* a, unsigned b0, unsigned b1) {
    asm volatile(
        "mma.sync.aligned.m16n8k16.row.col.f32.f16.f16.f32 "
        "{%0,%1,%2,%3}, {%4,%5,%6,%7}, {%8,%9}, {%0,%1,%2,%3};"
        : "+f"(d[0]), "+f"(d[1]), "+f"(d[2]), "+f"(d[3])
        : "r"(a[0]), "r"(a[1]), "r"(a[2]), "r"(a[3]), "r"(b0), "r"(b1));
}
__device__ __forceinline__ void mma16808(float* d, unsigned a0, unsigned a1, unsigned b0) {
    asm volatile(
        "mma.sync.aligned.m16n8k8.row.col.f32.f16.f16.f32 "
        "{%0,%1,%2,%3}, {%4,%5}, {%6}, {%0,%1,%2,%3};"
        : "+f"(d[0]), "+f"(d[1]), "+f"(d[2]), "+f"(d[3])
        : "r"(a0), "r"(a1), "r"(b0));
}
__device__ __forceinline__ float asqrt(float v) {
    float r;
    asm("sqrt.approx.f32 %0, %1;" : "=f"(r) : "f"(v));
    return r;
}
__device__ __forceinline__ float leaky(float v) { return v > 0.0f ? v : 0.01f * v; }
__device__ __forceinline__ unsigned short h16(float v) {
    __half h = __float2half_rn(v);
    return *(unsigned short*)&h;
}
__device__ __forceinline__ unsigned pack2(float a, float b) {
    __half2 h = __floats2half2_rn(a, b);
    return *(unsigned*)&h;
}

// Epilogue (8x1): leaky + fp16 into h plane (256B rows), re-init acc with bias.
__device__ __forceinline__ void epi_split(float (&acc)[16][4], unsigned char* dH,
                                          const float* nb, int w, int lane) {
    const int cp = lane & 3, r8 = lane >> 2;
    const int r1 = w * 16 + r8, r2 = r1 + 8;
    #pragma unroll
    for (int nfl = 0; nfl < 16; nfl++) {
        float* A = acc[nfl];
        const int c = nfl * 8 + cp * 2;
        unsigned short a0 = h16(leaky(A[0])), a1 = h16(leaky(A[1]));
        unsigned short a2 = h16(leaky(A[2])), a3 = h16(leaky(A[3]));
        const unsigned o1 = r1 * 256 + ((unsigned)(((c >> 3) ^ (r1 & 7))) << 4) + (c & 7) * 2;
        const unsigned o2 = r2 * 256 + ((unsigned)(((c >> 3) ^ (r2 & 7))) << 4) + (c & 7) * 2;
        *(unsigned*)(dH + o1) = (unsigned)a0 | ((unsigned)a1 << 16);
        *(unsigned*)(dH + o2) = (unsigned)a2 | ((unsigned)a3 << 16);
        A[0] = nb[c]; A[1] = nb[c + 1]; A[2] = nb[c]; A[3] = nb[c + 1];
    }
}

// ---------------------------------------------------------------------------
// Prep (+ output zero): rewrite weights into mma B-fragment order.
__global__ void k_prep(const float* __restrict__ W0, const float* __restrict__ W1,
                       const float* __restrict__ W2, float* __restrict__ out) {
    const int idx = blockIdx.x * 256 + threadIdx.x;
    const float* src; unsigned* dst; int t;
    if (idx < 65536)      { src = W0 + 9 * HH; dst = gBf;  t = idx; }
    else if (idx < 73728) { src = W1;          dst = gW1f; t = idx - 65536; }
    else if (idx < 81920) { src = W2;          dst = gW2f; t = idx - 73728; }
    else {
        int z = idx - 81920;
        if (z < BB * HH * 3) out[z] = 0.0f;
        return;
    }
    const int e = t >> 2, wsel = t & 3;
    const int ck = e >> 8, nfp = (e >> 5) & 7, l = e & 31;
    const int k0  = ck * 16 + 2 * (l & 3) + ((wsel & 1) ? 8 : 0);
    const int col = nfp * 16 + ((wsel >> 1) ? 8 : 0) + (l >> 2);
    const float v0 = src[(size_t)k0 * HH + col];
    const float v1 = src[(size_t)(k0 + 1) * HH + col];
    dst[t] = (unsigned)h16(v0) | ((unsigned)h16(v1) << 16);
}

// ---------------------------------------------------------------------------
__global__ void __launch_bounds__(256, 2)
k_main(const float* __restrict__ x, const float* __restrict__ u,
       const float* __restrict__ W0, const float* __restrict__ b0,
       const float* __restrict__ b1, const float* __restrict__ b2,
       float* __restrict__ out)
{
    extern __shared__ __align__(1024) unsigned char smem[];
    const unsigned sb = smem_u32(smem);
    const int tid = threadIdx.x, w = tid >> 5, lane = tid & 31;
    const int b = blockIdx.x >> 3, i0 = (blockIdx.x & 7) * 128;
    const int il = lane & 15, kq = lane >> 4;

    float* xall = (float*)(smem + OFF_XALL);
    float* nrm  = (float*)(smem + OFF_NRM);
    float* cu   = (float*)(smem + OFF_CU);
    float* w0n  = (float*)(smem + OFF_W0N);
    float* b1s  = (float*)(smem + OFF_B1S);
    float* b2s  = (float*)(smem + OFF_B2S);
    float* oacc = (float*)(smem + OFF_OACC);

    // prologue: whole-batch x into smem, biases, cu
    {
        const float4* src = (const float4*)(x + (size_t)b * NN * 3);
        float4* dst = (float4*)xall;
        #pragma unroll
        for (int m = 0; m < 3; m++) dst[tid + m * 256] = src[tid + m * 256];
    }
    if (tid < 128) {
        float s = b0[tid];
        #pragma unroll
        for (int g = 0; g < GG; g++) s += u[b * GG + g] * W0[g * HH + tid];
        cu[tid]  = s;
        w0n[tid] = W0[8 * HH + tid];
        b1s[tid] = b1[tid];
        b2s[tid] = b2[tid];
    }
    for (int t = tid; t < 384; t += 256) oacc[t] = 0.0f;
    __syncthreads();

    // Bj frag image (dot MMA B operands): jblock jb, lane ln -> half2 of X coords
    #pragma unroll
    for (int m = 0; m < 16; m++) {
        const int idx = tid + m * 256;            // 0..4095
        const int jb = idx >> 5, ln = idx & 31;
        const int c2 = (ln & 3) * 2, col = jb * 8 + (ln >> 2);
        const float v0 = (c2 < 3) ? xall[col * 3 + c2] : 0.0f;
        const float v1 = (c2 + 1 < 3) ? xall[col * 3 + c2 + 1] : 0.0f;
        *(unsigned*)(smem + OFF_BJ + idx * 4) = pack2(v0, v1);
    }
    if (tid < 128) {
        const float* y = xall + (size_t)(i0 + tid) * 3;
        nrm[tid] = asqrt(y[0] * y[0] + y[1] * y[1] + y[2] * y[2]);
    }
    __syncthreads();

    // Xi dot-A fragment (m16n8k8): warp w owns rows w*16..w*16+15
    unsigned xiA[2];
    {
        const int c2 = (lane & 3) * 2;
        const int r = w * 16 + (lane >> 2);
        const float* ya = xall + (size_t)(i0 + r) * 3;
        const float* yb = xall + (size_t)(i0 + r + 8) * 3;
        const float a0 = (c2 < 3) ? ya[c2] : 0.0f;
        const float a1 = (c2 + 1 < 3) ? ya[c2 + 1] : 0.0f;
        const float c0 = (c2 < 3) ? yb[c2] : 0.0f;
        const float c1 = (c2 + 1 < 3) ? yb[c2 + 1] : 0.0f;
        xiA[0] = pack2(a0, a1);
        xiA[1] = pack2(c0, c1);
    }

    // acc[nfl][4]: rows w*16 (+r8/+8), cols nfl*8 (+cp*2); init bias + u/norm features
    float acc[16][4];
    {
        const int cp = lane & 3, r8 = lane >> 2;
        const int r1 = w * 16 + r8, r2 = r1 + 8;
        const float n1 = nrm[r1], n2 = nrm[r2];
        #pragma unroll
        for (int nfl = 0; nfl < 16; nfl++) {
            const int c = nfl * 8 + cp * 2;
            float* A = acc[nfl];
            A[0] = cu[c]     + n1 * w0n[c];
            A[1] = cu[c + 1] + n1 * w0n[c + 1];
            A[2] = cu[c]     + n2 * w0n[c];
            A[3] = cu[c + 1] + n2 * w0n[c + 1];
        }
    }

    // ---------------- layer 0: barrier-free; warp-unique A gen (8x1) ----------------
    const unsigned bjBase = sb + OFF_BJ + (unsigned)lane * 4;
    const uint4* Bf = (const uint4*)gBf;
    for (int cb = 0; cb < 16; cb++) {
        const unsigned bjChunk = bjBase + (unsigned)cb * 1024;
        #pragma unroll
        for (int ks16 = 0; ks16 < 4; ks16++) {
            // B fragments: all 16 nf for this warp (8 x LDG.128, L1-shared across warps)
            const uint4* bp = Bf + (size_t)((cb * 4 + ks16) * 8 * 32 + lane);
            uint4 q[8];
            #pragma unroll
            for (int p = 0; p < 8; p++) q[p] = __ldg(bp + p * 32);
            // dot B frags (2 jblocks of 8)
            unsigned bj0, bj1;
            asm("ld.shared.b32 %0, [%1];" : "=r"(bj0) : "r"(bjChunk + (unsigned)ks16 * 256));
            asm("ld.shared.b32 %0, [%1];" : "=r"(bj1) : "r"(bjChunk + (unsigned)ks16 * 256 + 128));
            // dots (16 rows x 16 j)
            float d[2][4];
            d[0][0] = d[0][1] = d[0][2] = d[0][3] = 0.f;
            d[1][0] = d[1][1] = d[1][2] = d[1][3] = 0.f;
            mma16808(d[0], xiA[0], xiA[1], bj0);
            mma16808(d[1], xiA[0], xiA[1], bj1);
            // sqrt + pack -> A fragment (m16n8k16)
            unsigned af[4];
            af[0] = pack2(asqrt(d[0][0]), asqrt(d[0][1]));
            af[1] = pack2(asqrt(d[0][2]), asqrt(d[0][3]));
            af[2] = pack2(asqrt(d[1][0]), asqrt(d[1][1]));
            af[3] = pack2(asqrt(d[1][2]), asqrt(d[1][3]));
            // 16 main MMAs
            #pragma unroll
            for (int p = 0; p < 8; p++) {
                mma16816(acc[p * 2 + 0], af, q[p].x, q[p].y);
                mma16816(acc[p * 2 + 1], af, q[p].z, q[p].w);
            }
        }
    }
    __syncthreads();   // all warps done reading Bj before H overwrites it

    // layer MMA: A from smem H (ldsm), B fragments via LDG
    auto layer_mma = [&](const uint4* Wf) {
        #pragma unroll
        for (int kt = 0; kt < 8; kt++) {
            const uint4* bp = Wf + (size_t)(kt * 8 * 32 + lane);
            uint4 q[8];
            #pragma unroll
            for (int p = 0; p < 8; p++) q[p] = __ldg(bp + p * 32);
            unsigned a[4];
            const int kc = kt * 2 + kq;
            const int i = w * 16 + il;
            ldsm_x4(a, sb + OFF_H + i * 256 + ((unsigned)(kc ^ (i & 7)) << 4));
            #pragma unroll
            for (int p = 0; p < 8; p++) {
                mma16816(acc[p * 2 + 0], a, q[p].x, q[p].y);
                mma16816(acc[p * 2 + 1], a, q[p].z, q[p].w);
            }
        }
    };

    // ---------------- layer 0 epilogue -> H; layer 1 ----------------
    epi_split(acc, smem + OFF_H, b1s, w, lane);
    __syncthreads();
    layer_mma((const uint4*)gW1f);
    __syncthreads();

    // ---------------- layer 1 epilogue -> H; layer 2 ----------------
    epi_split(acc, smem + OFF_H, b2s, w, lane);
    __syncthreads();
    layer_mma((const uint4*)gW2f);

    // ---------------- final contraction ----------------
    {
        const int r8 = lane >> 2;
        const int r1 = w * 16 + r8, r2 = r1 + 8;
        const float* ya = xall + (size_t)(i0 + r1) * 3;
        const float* yb = xall + (size_t)(i0 + r2) * 3;
        const float x10 = ya[0], x11 = ya[1], x12 = ya[2];
        const float x20 = yb[0], x21 = yb[1], x22 = yb[2];
        #pragma unroll
        for (int nfl = 0; nfl < 16; nfl++) {
            float* A = acc[nfl];
            float s[6];
            s[0] = A[0] * x10 + A[2] * x20;
            s[1] = A[0] * x11 + A[2] * x21;
            s[2] = A[0] * x12 + A[2] * x22;
            s[3] = A[1] * x10 + A[3] * x20;
            s[4] = A[1] * x11 + A[3] * x21;
            s[5] = A[1] * x12 + A[3] * x22;
            #pragma unroll
            for (int q = 0; q < 6; q++) {
                s[q] += __shfl_xor_sync(0xffffffffu, s[q], 4);
                s[q] += __shfl_xor_sync(0xffffffffu, s[q], 8);
                s[q] += __shfl_xor_sync(0xffffffffu, s[q], 16);
            }
            if (lane < 4) {
                const int c = nfl * 8 + lane * 2;
                atomicAdd(&oacc[c * 3 + 0], s[0]);
                atomicAdd(&oacc[c * 3 + 1], s[1]);
                atomicAdd(&oacc[c * 3 + 2], s[2]);
                atomicAdd(&oacc[(c + 1) * 3 + 0], s[3]);
                atomicAdd(&oacc[(c + 1) * 3 + 1], s[4]);
                atomicAdd(&oacc[(c + 1) * 3 + 2], s[5]);
            }
        }
    }
    __syncthreads();
    const float inv = 1.0f / (float)NN;
    for (int t = tid; t < 384; t += 256)
        atomicAdd(out + (size_t)b * 384 + t, oacc[t] * inv);
}

// ---------------------------------------------------------------------------
extern "C" void kernel_launch(void* const* d_in, const int* in_sizes, int n_in,
                              void* d_out, int out_size) {
    const float* x  = (const float*)d_in[0];
    const float* u  = (const float*)d_in[1];
    const float* W0 = (const float*)d_in[2];
    const float* b0 = (const float*)d_in[3];
    const float* W1 = (const float*)d_in[4];
    const float* b1 = (const float*)d_in[5];
    const float* W2 = (const float*)d_in[6];
    const float* b2 = (const float*)d_in[7];
    float* out = (float*)d_out;

    cudaFuncSetAttribute(k_main, cudaFuncAttributeMaxDynamicSharedMemorySize, SMEM_BYTES);

    k_prep<<<368, 256>>>(W0, W1, W2, out);
    k_main<<<BB * (NN / 128), 256, SMEM_BYTES>>>(x, u, W0, b0, b1, b2, out);
}